// round 3
// baseline (speedup 1.0000x reference)
#include <cuda_runtime.h>
#include <cstdint>
#include <cstdio>

#define S_LEN 1024
#define B_SZ  128
#define D_IN  256
#define H_SZ  512
#define C_OUT 128

typedef unsigned long long ull;

// ---------------- f32x2 packed-FMA helpers (sm_103a FFMA2) ----------------
__device__ __forceinline__ ull ffma2(ull a, ull b, ull c) {
    ull d;
    asm("fma.rn.f32x2 %0, %1, %2, %3;" : "=l"(d) : "l"(a), "l"(b), "l"(c));
    return d;
}
__device__ __forceinline__ ull dup2(float v) {
    ull d;
    asm("mov.b64 %0, {%1, %1};" : "=l"(d) : "f"(v));
    return d;
}
__device__ __forceinline__ float2 unpack2(ull p) {
    float2 r;
    asm("mov.b64 {%0, %1}, %2;" : "=f"(r.x), "=f"(r.y) : "l"(p));
    return r;
}

// ---------------- device scratch ----------------
__device__ float g_T[(size_t)S_LEN * B_SZ * H_SZ];   // x@W_tau_x + b_tau_lin + b_tau
__device__ float g_G[(size_t)S_LEN * B_SZ * H_SZ];   // x@W_in + b_in
__device__ float g_mem[B_SZ * H_SZ];
__device__ int   g_cnt;

__global__ void init_kernel() { g_cnt = 0; }

// ---------------- Phase 1: fused precompute GEMM (f32x2) ----------------
__global__ __launch_bounds__(256, 2) void phase1_kernel(
    const float* __restrict__ x, const float* __restrict__ Win,
    const float* __restrict__ bin, const float* __restrict__ Wtau,
    const float* __restrict__ btl, const float* __restrict__ bt)
{
    __shared__ float As[2][16][128];   // As[k][m]
    __shared__ float Bs[2][16][128];   // Bs[k][n]

    const int tid = threadIdx.x;
    const int m0 = blockIdx.y * 128;
    const int n0 = blockIdx.x * 128;
    const bool isG = (n0 < 512);
    const float* __restrict__ Bp = isG ? (Win + n0) : (Wtau + (n0 - 512));

    const int q0 = tid, q1 = tid + 256;
    const int ar0 = q0 >> 2, ak0 = (q0 & 3) * 4;
    const int ar1 = q1 >> 2, ak1 = (q1 & 3) * 4;
    const int m_0 = m0 + ar0, m_1 = m0 + ar1;
    const float* ap0 = x + ((size_t)(m_0 & 127) * 1024 + (m_0 >> 7)) * 256 + ak0;
    const float* ap1 = x + ((size_t)(m_1 & 127) * 1024 + (m_1 >> 7)) * 256 + ak1;
    const int bk0 = q0 >> 5, bn0 = (q0 & 31) * 4;
    const int bk1 = q1 >> 5, bn1 = (q1 & 31) * 4;

    const int tx = tid & 15, ty = tid >> 4;
    const int c0 = tx * 4, c1 = tx * 4 + 64;
    const int r0 = ty * 4, r1 = ty * 4 + 64;

    ull acc2[8][4];
#pragma unroll
    for (int i = 0; i < 8; i++)
#pragma unroll
        for (int j = 0; j < 4; j++) acc2[i][j] = 0ull;

    float4 pa0 = *(const float4*)(ap0);
    float4 pa1 = *(const float4*)(ap1);
    float4 pb0 = *(const float4*)(Bp + (size_t)bk0 * 512 + bn0);
    float4 pb1 = *(const float4*)(Bp + (size_t)bk1 * 512 + bn1);

    As[0][ak0 + 0][ar0] = pa0.x; As[0][ak0 + 1][ar0] = pa0.y;
    As[0][ak0 + 2][ar0] = pa0.z; As[0][ak0 + 3][ar0] = pa0.w;
    As[0][ak1 + 0][ar1] = pa1.x; As[0][ak1 + 1][ar1] = pa1.y;
    As[0][ak1 + 2][ar1] = pa1.z; As[0][ak1 + 3][ar1] = pa1.w;
    *(float4*)&Bs[0][bk0][bn0] = pb0;
    *(float4*)&Bs[0][bk1][bn1] = pb1;
    __syncthreads();

    int p = 0;
    for (int kt = 0; kt < 16; kt++) {
        if (kt < 15) {
            const int kc = (kt + 1) * 16;
            pa0 = *(const float4*)(ap0 + kc);
            pa1 = *(const float4*)(ap1 + kc);
            pb0 = *(const float4*)(Bp + (size_t)(kc + bk0) * 512 + bn0);
            pb1 = *(const float4*)(Bp + (size_t)(kc + bk1) * 512 + bn1);
        }
#pragma unroll
        for (int k = 0; k < 16; k++) {
            float4 a0 = *(const float4*)&As[p][k][r0];
            float4 a1 = *(const float4*)&As[p][k][r1];
            const ull* bu0 = (const ull*)&Bs[p][k][c0];
            const ull* bu1 = (const ull*)&Bs[p][k][c1];
            ull bv[4] = {bu0[0], bu0[1], bu1[0], bu1[1]};
            float av[8] = {a0.x, a0.y, a0.z, a0.w, a1.x, a1.y, a1.z, a1.w};
#pragma unroll
            for (int i = 0; i < 8; i++) {
                const ull ad = dup2(av[i]);
#pragma unroll
                for (int j = 0; j < 4; j++)
                    acc2[i][j] = ffma2(ad, bv[j], acc2[i][j]);
            }
        }
        if (kt < 15) {
            const int np = p ^ 1;
            As[np][ak0 + 0][ar0] = pa0.x; As[np][ak0 + 1][ar0] = pa0.y;
            As[np][ak0 + 2][ar0] = pa0.z; As[np][ak0 + 3][ar0] = pa0.w;
            As[np][ak1 + 0][ar1] = pa1.x; As[np][ak1 + 1][ar1] = pa1.y;
            As[np][ak1 + 2][ar1] = pa1.z; As[np][ak1 + 3][ar1] = pa1.w;
            *(float4*)&Bs[np][bk0][bn0] = pb0;
            *(float4*)&Bs[np][bk1][bn1] = pb1;
        }
        __syncthreads();
        p ^= 1;
    }

    float* dst = isG ? g_G : g_T;
    const int coloff = isG ? n0 : (n0 - 512);
    float bias[8];
#pragma unroll
    for (int j = 0; j < 8; j++) {
        const int ncol = (j < 4) ? (c0 + j) : (c1 + j - 4);
        const int gb = coloff + ncol;
        bias[j] = isG ? bin[gb] : (btl[gb] + bt[gb]);
    }
#pragma unroll
    for (int i = 0; i < 8; i++) {
        const int mrow = m0 + ((i < 4) ? (r0 + i) : (r1 + i - 4));
        float2 u0 = unpack2(acc2[i][0]);
        float2 u1 = unpack2(acc2[i][1]);
        float2 u2 = unpack2(acc2[i][2]);
        float2 u3 = unpack2(acc2[i][3]);
        float4 o0 = make_float4(u0.x + bias[0], u0.y + bias[1],
                                u1.x + bias[2], u1.y + bias[3]);
        float4 o1 = make_float4(u2.x + bias[4], u2.y + bias[5],
                                u3.x + bias[6], u3.y + bias[7]);
        *(float4*)(dst + (size_t)mrow * 512 + coloff + c0) = o0;
        *(float4*)(dst + (size_t)mrow * 512 + coloff + c1) = o1;
    }
}

// ---------------- Phase 2: persistent recurrent kernel (clusters of 8, f32x2) ----------------
__device__ __forceinline__ unsigned smem_u32_addr(const void* p) {
    unsigned a;
    asm("{ .reg .u64 t; cvta.to.shared.u64 t, %1; cvt.u32.u64 %0, t; }"
        : "=r"(a) : "l"(p));
    return a;
}

#define CLUSTER_BARRIER() \
    asm volatile("barrier.cluster.arrive.aligned;\n\tbarrier.cluster.wait.aligned;" ::: "memory")

__global__ void __cluster_dims__(8, 1, 1) __launch_bounds__(256, 1)
recurrent_kernel(const float* __restrict__ Wtau)
{
    extern __shared__ float sm[];
    float* Wm   = sm;                     // [512][64]       128 KB
    float* memT = sm + 512 * 64;          // [2][512][8]      32 KB  (h-major, batch contiguous)
    float* part = memT + 2 * 512 * 8;     // [8][8][64]       16 KB  (warp, batch, col)

    const int tid  = threadIdx.x;
    const int lane = tid & 31;
    const int w    = tid >> 5;
    const int r    = blockIdx.x & 7;          // rank -> column slice
    const int b0   = (blockIdx.x >> 3) * 8;   // cluster -> 8 batch rows

    // Load W_tau_m slice: rows 256..767, cols r*64..r*64+63
    for (int idx = tid; idx < 512 * 64; idx += 256) {
        const int k = idx >> 6, c = idx & 63;
        Wm[idx] = Wtau[(size_t)(256 + k) * 512 + r * 64 + c];
    }
    for (int idx = tid; idx < 2 * 512 * 8; idx += 256) memT[idx] = 0.f;

    const unsigned memT_base = smem_u32_addr(memT);
    // hoisted mapa: remote base addresses of memT in each cluster CTA
    unsigned rbase[8];
#pragma unroll
    for (int pr = 0; pr < 8; pr++)
        asm("mapa.shared::cluster.u32 %0, %1, %2;" : "=r"(rbase[pr]) : "r"(memT_base), "r"(pr));

    CLUSTER_BARRIER();

    // elementwise role: cells (bl, ce) and (bl+1, ce), adjacent batches -> 64-bit packed bcast
    const int ce = tid & 63;
    const int bl = (tid >> 6) * 2;
    const int gh = r * 64 + ce;                 // global hidden col of my cells
    const int k0 = w * 64;                      // warp K-split

    float cnt = 0.f;

    for (int t = 0; t < S_LEN; t++) {
        const int p = t & 1;

        // prefetch T/G (consumed after GEMM; ~2k cycles of cover)
        const size_t row0 = ((size_t)t * B_SZ + b0 + bl) * H_SZ + gh;
        const size_t row1 = ((size_t)t * B_SZ + b0 + bl + 1) * H_SZ + gh;
        const float Tv0 = g_T[row0], Gv0 = g_G[row0];
        const float Tv1 = g_T[row1], Gv1 = g_G[row1];

        const float* mrow = memT + p * (512 * 8);

        // ---- GEMM: out[b][c] = sum_k memT[k][b] * Wm[k][c], packed over batch pairs ----
        ull acc_a[4], acc_b[4];
#pragma unroll
        for (int q = 0; q < 4; q++) { acc_a[q] = 0ull; acc_b[q] = 0ull; }

        const float* mp = mrow + k0 * 8;
        const float* wp = Wm + k0 * 64;
#pragma unroll 8
        for (int kk = 0; kk < 64; kk++) {
            ulonglong2 ma = *(const ulonglong2*)(mp + kk * 8);       // batches 0-3 (broadcast)
            ulonglong2 mb = *(const ulonglong2*)(mp + kk * 8 + 4);   // batches 4-7
            const float w0 = wp[kk * 64 + lane];
            const float w1 = wp[kk * 64 + lane + 32];
            const ull w0d = dup2(w0);
            const ull w1d = dup2(w1);
            acc_a[0] = ffma2(ma.x, w0d, acc_a[0]);
            acc_a[1] = ffma2(ma.y, w0d, acc_a[1]);
            acc_a[2] = ffma2(mb.x, w0d, acc_a[2]);
            acc_a[3] = ffma2(mb.y, w0d, acc_a[3]);
            acc_b[0] = ffma2(ma.x, w1d, acc_b[0]);
            acc_b[1] = ffma2(ma.y, w1d, acc_b[1]);
            acc_b[2] = ffma2(mb.x, w1d, acc_b[2]);
            acc_b[3] = ffma2(mb.y, w1d, acc_b[3]);
        }
        // write warp partials: part[w][b][c]
#pragma unroll
        for (int q = 0; q < 4; q++) {
            float2 fa = unpack2(acc_a[q]);
            float2 fb = unpack2(acc_b[q]);
            part[w * 512 + (2 * q)     * 64 + lane]      = fa.x;
            part[w * 512 + (2 * q + 1) * 64 + lane]      = fa.y;
            part[w * 512 + (2 * q)     * 64 + lane + 32] = fb.x;
            part[w * 512 + (2 * q + 1) * 64 + lane + 32] = fb.y;
        }
        __syncthreads();

        // ---- reduce 8 warp partials + elementwise update for cells (bl, ce), (bl+1, ce) ----
        float s0 = 0.f, s1 = 0.f;
#pragma unroll
        for (int ww = 0; ww < 8; ww++) {
            s0 += part[ww * 512 + bl * 64 + ce];
            s1 += part[ww * 512 + (bl + 1) * 64 + ce];
        }
        const float l0 = Tv0 + s0, l1 = Tv1 + s1;
        float beta0 = 1.f / (1.f + expf(-l0));
        float beta1 = 1.f / (1.f + expf(-l1));
        beta0 = fminf(fmaxf(beta0, 0.01f), 0.99f);
        beta1 = fminf(fmaxf(beta1, 0.01f), 0.99f);
        const float mo0 = mrow[gh * 8 + bl];
        const float mo1 = mrow[gh * 8 + bl + 1];
        float mn0 = fmaf(beta0, mo0, Gv0);
        float mn1 = fmaf(beta1, mo1, Gv1);
        const float sp0 = ((mn0 - 1.0f) > 0.0f) ? 1.f : 0.f;
        const float sp1 = ((mn1 - 1.0f) > 0.0f) ? 1.f : 0.f;
        mn0 -= sp0; mn1 -= sp1;
        cnt += sp0 + sp1;

        // ---- packed broadcast of (mn0, mn1) into every cluster CTA's buffer p^1 ----
        ull pk;
        asm("mov.b64 %0, {%1, %2};" : "=l"(pk) : "f"(mn0), "f"(mn1));
        const unsigned off = (unsigned)(((p ^ 1) * (512 * 8) + gh * 8 + bl) * 4);
#pragma unroll
        for (int pr = 0; pr < 8; pr++) {
            asm volatile("st.shared::cluster.u64 [%0], %1;"
                         :: "r"(rbase[pr] + off), "l"(pk));
        }
        CLUSTER_BARRIER();
    }

    // final mem is in buffer 0 (t=1023: p=1, wrote p^1=0)
    if (r == 0) {
        for (int idx = tid; idx < 512 * 8; idx += 256) {
            const int h = idx >> 3, b = idx & 7;
            g_mem[(size_t)(b0 + b) * 512 + h] = memT[idx];
        }
    }

    // spike-count reduction
    __syncthreads();
    part[tid] = cnt;
    __syncthreads();
    if (tid < 128) part[tid] += part[tid + 128];
    __syncthreads();
    if (tid < 64) part[tid] += part[tid + 64];
    __syncthreads();
    if (tid < 32) {
        float v = part[tid] + part[tid + 32];
#pragma unroll
        for (int o = 16; o > 0; o >>= 1) v += __shfl_down_sync(0xffffffffu, v, o);
        if (tid == 0) atomicAdd(&g_cnt, (int)(v + 0.5f));
    }
}

// ---------------- Phase 3: readout GEMM + sparsity ----------------
__global__ void readout_kernel(const float* __restrict__ Wro, const float* __restrict__ bro,
                               float* __restrict__ out, int out_size)
{
    __shared__ float mrow[512];
    const int row = blockIdx.x;
    const int tid = threadIdx.x;   // 128
    for (int i = tid; i < 512; i += 128) mrow[i] = g_mem[(size_t)row * 512 + i];
    __syncthreads();
    float acc = bro[tid];
#pragma unroll 8
    for (int k = 0; k < 512; k++)
        acc = fmaf(mrow[k], Wro[(size_t)k * 128 + tid], acc);
    out[(size_t)row * 128 + tid] = acc;
    if (row == 0 && tid == 0 && out_size > B_SZ * C_OUT) {
        out[B_SZ * C_OUT] = 1.0f - (float)g_cnt / (float)((size_t)S_LEN * B_SZ * H_SZ);
    }
}

// ---------------- launch ----------------
extern "C" void kernel_launch(void* const* d_in, const int* in_sizes, int n_in,
                              void* d_out, int out_size)
{
    const float* x    = (const float*)d_in[0];
    const float* Win  = (const float*)d_in[1];
    const float* bin  = (const float*)d_in[2];
    const float* Wtau = (const float*)d_in[3];
    const float* btl  = (const float*)d_in[4];
    const float* bt   = (const float*)d_in[5];
    const float* Wro  = (const float*)d_in[6];
    const float* bro  = (const float*)d_in[7];

    init_kernel<<<1, 1>>>();

    dim3 g1(8, 1024);   // n-tiles x m-tiles
    phase1_kernel<<<g1, 256>>>(x, Win, bin, Wtau, btl, bt);

    const int rec_smem = (512 * 64 + 2 * 512 * 8 + 8 * 512) * (int)sizeof(float); // 180224 B
    cudaFuncSetAttribute(recurrent_kernel, cudaFuncAttributeMaxDynamicSharedMemorySize, rec_smem);
    recurrent_kernel<<<128, 256, rec_smem>>>(Wtau);

    readout_kernel<<<B_SZ, C_OUT>>>(Wro, bro, (float*)d_out, out_size);
}

// round 4
// speedup vs baseline: 1.1510x; 1.1510x over previous
#include <cuda_runtime.h>
#include <cstdint>
#include <cstdio>

#define S_LEN 1024
#define B_SZ  128
#define D_IN  256
#define H_SZ  512
#define C_OUT 128

// ---------------- device scratch ----------------
__device__ float g_T[(size_t)S_LEN * B_SZ * H_SZ];   // x@W_tau_x + b_tau_lin + b_tau
__device__ float g_G[(size_t)S_LEN * B_SZ * H_SZ];   // x@W_in + b_in
__device__ float g_buf[2 * 16 * 512 * 8];            // mem exchange: [phase][cluster][h][b]
__device__ int   g_cnt;

__global__ void init_kernel() { g_cnt = 0; }

// ---------------- Phase 1: fused precompute GEMM (scalar fp32, R2-proven) ----------------
__global__ __launch_bounds__(256, 2) void phase1_kernel(
    const float* __restrict__ x, const float* __restrict__ Win,
    const float* __restrict__ bin, const float* __restrict__ Wtau,
    const float* __restrict__ btl, const float* __restrict__ bt)
{
    __shared__ float As[2][16][128];   // As[k][m]
    __shared__ float Bs[2][16][128];   // Bs[k][n]

    const int tid = threadIdx.x;
    const int m0 = blockIdx.y * 128;
    const int n0 = blockIdx.x * 128;
    const bool isG = (n0 < 512);
    const float* __restrict__ Bp = isG ? (Win + n0) : (Wtau + (n0 - 512));

    const int q0 = tid, q1 = tid + 256;
    const int ar0 = q0 >> 2, ak0 = (q0 & 3) * 4;
    const int ar1 = q1 >> 2, ak1 = (q1 & 3) * 4;
    const int m_0 = m0 + ar0, m_1 = m0 + ar1;
    const float* ap0 = x + ((size_t)(m_0 & 127) * 1024 + (m_0 >> 7)) * 256 + ak0;
    const float* ap1 = x + ((size_t)(m_1 & 127) * 1024 + (m_1 >> 7)) * 256 + ak1;
    const int bk0 = q0 >> 5, bn0 = (q0 & 31) * 4;
    const int bk1 = q1 >> 5, bn1 = (q1 & 31) * 4;

    const int tx = tid & 15, ty = tid >> 4;
    const int c0 = tx * 4, c1 = tx * 4 + 64;
    const int r0 = ty * 4, r1 = ty * 4 + 64;

    float acc[8][8];
#pragma unroll
    for (int i = 0; i < 8; i++)
#pragma unroll
        for (int j = 0; j < 8; j++) acc[i][j] = 0.f;

    float4 pa0 = *(const float4*)(ap0);
    float4 pa1 = *(const float4*)(ap1);
    float4 pb0 = *(const float4*)(Bp + (size_t)bk0 * 512 + bn0);
    float4 pb1 = *(const float4*)(Bp + (size_t)bk1 * 512 + bn1);

    As[0][ak0 + 0][ar0] = pa0.x; As[0][ak0 + 1][ar0] = pa0.y;
    As[0][ak0 + 2][ar0] = pa0.z; As[0][ak0 + 3][ar0] = pa0.w;
    As[0][ak1 + 0][ar1] = pa1.x; As[0][ak1 + 1][ar1] = pa1.y;
    As[0][ak1 + 2][ar1] = pa1.z; As[0][ak1 + 3][ar1] = pa1.w;
    *(float4*)&Bs[0][bk0][bn0] = pb0;
    *(float4*)&Bs[0][bk1][bn1] = pb1;
    __syncthreads();

    int p = 0;
    for (int kt = 0; kt < 16; kt++) {
        if (kt < 15) {
            const int kc = (kt + 1) * 16;
            pa0 = *(const float4*)(ap0 + kc);
            pa1 = *(const float4*)(ap1 + kc);
            pb0 = *(const float4*)(Bp + (size_t)(kc + bk0) * 512 + bn0);
            pb1 = *(const float4*)(Bp + (size_t)(kc + bk1) * 512 + bn1);
        }
#pragma unroll
        for (int k = 0; k < 16; k++) {
            float4 a0 = *(const float4*)&As[p][k][r0];
            float4 a1 = *(const float4*)&As[p][k][r1];
            float4 b0 = *(const float4*)&Bs[p][k][c0];
            float4 b1 = *(const float4*)&Bs[p][k][c1];
            float av[8] = {a0.x, a0.y, a0.z, a0.w, a1.x, a1.y, a1.z, a1.w};
            float bv[8] = {b0.x, b0.y, b0.z, b0.w, b1.x, b1.y, b1.z, b1.w};
#pragma unroll
            for (int i = 0; i < 8; i++)
#pragma unroll
                for (int j = 0; j < 8; j++)
                    acc[i][j] = fmaf(av[i], bv[j], acc[i][j]);
        }
        if (kt < 15) {
            const int np = p ^ 1;
            As[np][ak0 + 0][ar0] = pa0.x; As[np][ak0 + 1][ar0] = pa0.y;
            As[np][ak0 + 2][ar0] = pa0.z; As[np][ak0 + 3][ar0] = pa0.w;
            As[np][ak1 + 0][ar1] = pa1.x; As[np][ak1 + 1][ar1] = pa1.y;
            As[np][ak1 + 2][ar1] = pa1.z; As[np][ak1 + 3][ar1] = pa1.w;
            *(float4*)&Bs[np][bk0][bn0] = pb0;
            *(float4*)&Bs[np][bk1][bn1] = pb1;
        }
        __syncthreads();
        p ^= 1;
    }

    float* dst = isG ? g_G : g_T;
    const int coloff = isG ? n0 : (n0 - 512);
    float bias[8];
#pragma unroll
    for (int j = 0; j < 8; j++) {
        const int ncol = (j < 4) ? (c0 + j) : (c1 + j - 4);
        const int gb = coloff + ncol;
        bias[j] = isG ? bin[gb] : (btl[gb] + bt[gb]);
    }
#pragma unroll
    for (int i = 0; i < 8; i++) {
        const int mrow = m0 + ((i < 4) ? (r0 + i) : (r1 + i - 4));
        float4 o0 = make_float4(acc[i][0] + bias[0], acc[i][1] + bias[1],
                                acc[i][2] + bias[2], acc[i][3] + bias[3]);
        float4 o1 = make_float4(acc[i][4] + bias[4], acc[i][5] + bias[5],
                                acc[i][6] + bias[6], acc[i][7] + bias[7]);
        *(float4*)(dst + (size_t)mrow * 512 + coloff + c0) = o0;
        *(float4*)(dst + (size_t)mrow * 512 + coloff + c1) = o1;
    }
}

// ---------------- Phase 2: persistent recurrent kernel ----------------
__device__ __forceinline__ unsigned smem_u32_addr(const void* p) {
    unsigned a;
    asm("{ .reg .u64 t; cvta.to.shared.u64 t, %1; cvt.u32.u64 %0, t; }"
        : "=r"(a) : "l"(p));
    return a;
}

#define CLUSTER_BARRIER() \
    asm volatile("barrier.cluster.arrive.aligned;\n\tbarrier.cluster.wait.aligned;" ::: "memory")

__global__ void __cluster_dims__(8, 1, 1) __launch_bounds__(256, 1)
recurrent_kernel(const float* __restrict__ Wtau)
{
    extern __shared__ float sm[];
    float* Wm   = sm;                     // [512][64]   128 KB
    float* memT = sm + 512 * 64;          // [512][8]     16 KB  (h-major, batch contiguous)
    float* part = memT + 512 * 8;         // [8][8][64]   16 KB  (warp, batch, col)
    // mbarrier lives right after part (8 bytes, 8-aligned)
    unsigned long long* mbar = (unsigned long long*)(part + 8 * 512);

    const int tid  = threadIdx.x;
    const int lane = tid & 31;
    const int w    = tid >> 5;
    const int r    = blockIdx.x & 7;          // rank -> column slice
    const int cl   = blockIdx.x >> 3;         // cluster index -> 8 batch rows
    const int b0   = cl * 8;

    float* gb0 = g_buf + (size_t)cl * 4096;             // phase-0 buffer region
    float* gb1 = g_buf + (size_t)(16 + cl) * 4096;      // phase-1 buffer region

    // Load W_tau_m slice: rows 256..767, cols r*64..r*64+63
    for (int idx = tid; idx < 512 * 64; idx += 256) {
        const int k = idx >> 6, c = idx & 63;
        Wm[idx] = Wtau[(size_t)(256 + k) * 512 + r * 64 + c];
    }
    // Zero mem staging buffer (t=0 input)
    for (int idx = tid; idx < 512 * 8; idx += 256) memT[idx] = 0.f;

    const unsigned mbar_addr = smem_u32_addr(mbar);
    if (tid == 0) {
        asm volatile("mbarrier.init.shared.b64 [%0], %1;"
                     :: "r"(mbar_addr), "r"(64) : "memory");  // 8 warps x 8 CTAs
    }
    // hoisted mapa: this mbar's address in every cluster CTA
    unsigned rmb[8];
#pragma unroll
    for (int pr = 0; pr < 8; pr++)
        asm("mapa.shared::cluster.u32 %0, %1, %2;" : "=r"(rmb[pr]) : "r"(mbar_addr), "r"(pr));

    CLUSTER_BARRIER();   // mbar init + memT zero visible cluster-wide

    // elementwise role: cells (bl, ce) and (bl+1, ce)
    const int ce = tid & 63;
    const int bl = (tid >> 6) * 2;
    const int gh = r * 64 + ce;                 // global hidden col of my cells
    const int k0 = w * 64;                      // warp K-split

    float cnt = 0.f;

    for (int t = 0; t < S_LEN; t++) {
        // ---- stage mem from gmem (t=0: memT already zeros) ----
        if (t > 0) {
            const float* src = (t & 1) ? gb1 : gb0;
            float4 a0 = __ldcg((const float4*)(src + tid * 16));
            float4 a1 = __ldcg((const float4*)(src + tid * 16 + 4));
            float4 a2 = __ldcg((const float4*)(src + tid * 16 + 8));
            float4 a3 = __ldcg((const float4*)(src + tid * 16 + 12));
            float4* md = (float4*)(memT + tid * 16);
            md[0] = a0; md[1] = a1; md[2] = a2; md[3] = a3;
            __syncthreads();
        }

        // prefetch T/G (consumed after GEMM; hidden behind ~4k cycles)
        const size_t row0 = ((size_t)t * B_SZ + b0 + bl) * H_SZ + gh;
        const size_t row1 = ((size_t)t * B_SZ + b0 + bl + 1) * H_SZ + gh;
        const float Tv0 = g_T[row0], Gv0 = g_G[row0];
        const float Tv1 = g_T[row1], Gv1 = g_G[row1];

        // ---- GEMM: out[b][c] = sum_k memT[k][b] * Wm[k][c] (warp K-split) ----
        unsigned long long dummy;
        float acc_a[8], acc_b[8];
#pragma unroll
        for (int b = 0; b < 8; b++) { acc_a[b] = 0.f; acc_b[b] = 0.f; }

        const float* mp = memT + k0 * 8;
        const float* wp = Wm + k0 * 64;
#pragma unroll 4
        for (int kk = 0; kk < 64; kk += 4) {
            float rm[4][8];
#pragma unroll
            for (int j = 0; j < 4; j++) {
                float4 v0 = *(const float4*)(mp + (kk + j) * 8);
                float4 v1 = *(const float4*)(mp + (kk + j) * 8 + 4);
                rm[j][0] = v0.x; rm[j][1] = v0.y; rm[j][2] = v0.z; rm[j][3] = v0.w;
                rm[j][4] = v1.x; rm[j][5] = v1.y; rm[j][6] = v1.z; rm[j][7] = v1.w;
            }
#pragma unroll
            for (int j = 0; j < 4; j++) {
                const float w0 = wp[(kk + j) * 64 + lane];
                const float w1 = wp[(kk + j) * 64 + lane + 32];
#pragma unroll
                for (int b = 0; b < 8; b++) {
                    acc_a[b] = fmaf(rm[j][b], w0, acc_a[b]);
                    acc_b[b] = fmaf(rm[j][b], w1, acc_b[b]);
                }
            }
        }
        (void)dummy;
        // write warp partials: part[w][b][c]
#pragma unroll
        for (int b = 0; b < 8; b++) {
            part[w * 512 + b * 64 + lane]      = acc_a[b];
            part[w * 512 + b * 64 + lane + 32] = acc_b[b];
        }
        __syncthreads();

        // ---- reduce 8 warp partials + elementwise update ----
        float s0 = 0.f, s1 = 0.f;
#pragma unroll
        for (int ww = 0; ww < 8; ww++) {
            s0 += part[ww * 512 + bl * 64 + ce];
            s1 += part[ww * 512 + (bl + 1) * 64 + ce];
        }
        const float l0 = Tv0 + s0, l1 = Tv1 + s1;
        float beta0 = 1.f / (1.f + expf(-l0));
        float beta1 = 1.f / (1.f + expf(-l1));
        beta0 = fminf(fmaxf(beta0, 0.01f), 0.99f);
        beta1 = fminf(fmaxf(beta1, 0.01f), 0.99f);
        const float mo0 = memT[gh * 8 + bl];
        const float mo1 = memT[gh * 8 + bl + 1];
        float mn0 = fmaf(beta0, mo0, Gv0);
        float mn1 = fmaf(beta1, mo1, Gv1);
        const float sp0 = ((mn0 - 1.0f) > 0.0f) ? 1.f : 0.f;
        const float sp1 = ((mn1 - 1.0f) > 0.0f) ? 1.f : 0.f;
        mn0 -= sp0; mn1 -= sp1;
        cnt += sp0 + sp1;

        // ---- publish slice to L2 (write buffer for step t+1) ----
        float* dst = ((t + 1) & 1) ? gb1 : gb0;
        asm volatile("st.global.cg.v2.f32 [%0], {%1, %2};"
                     :: "l"(dst + gh * 8 + bl), "f"(mn0), "f"(mn1) : "memory");
        __syncwarp();
        if (lane == 0) {
            __threadfence();   // cumulative: releases the whole warp's STGs
#pragma unroll
            for (int pr = 0; pr < 8; pr++)
                asm volatile("mbarrier.arrive.shared::cluster.b64 _, [%0];"
                             :: "r"(rmb[pr]) : "memory");
        }
        // ---- wait: all 64 warps (8 CTAs x 8 warps) arrived ----
        {
            const unsigned ph = (unsigned)(t & 1);
            asm volatile(
                "{\n\t"
                ".reg .pred P;\n\t"
                "W_%=:\n\t"
                "mbarrier.try_wait.parity.acquire.cluster.shared::cta.b64 P, [%0], %1, 0x989680;\n\t"
                "@P bra D_%=;\n\t"
                "bra W_%=;\n\t"
                "D_%=:\n\t"
                "}"
                :: "r"(mbar_addr), "r"(ph) : "memory");
        }
    }

    // spike-count reduction
    __syncthreads();
    part[tid] = cnt;
    __syncthreads();
    if (tid < 128) part[tid] += part[tid + 128];
    __syncthreads();
    if (tid < 64) part[tid] += part[tid + 64];
    __syncthreads();
    if (tid < 32) {
        float v = part[tid] + part[tid + 32];
#pragma unroll
        for (int o = 16; o > 0; o >>= 1) v += __shfl_down_sync(0xffffffffu, v, o);
        if (tid == 0) atomicAdd(&g_cnt, (int)(v + 0.5f));
    }
    CLUSTER_BARRIER();   // clean cluster exit
}

// ---------------- Phase 3: readout GEMM + sparsity ----------------
// final mem (t=1023 wrote buffer 0): mem[b][h] = g_buf[(b>>3)*4096 + h*8 + (b&7)]
__global__ void readout_kernel(const float* __restrict__ Wro, const float* __restrict__ bro,
                               float* __restrict__ out, int out_size)
{
    __shared__ float mrow[512];
    const int row = blockIdx.x;
    const int tid = threadIdx.x;   // 128
    const float* src = g_buf + (size_t)(row >> 3) * 4096 + (row & 7);
    for (int i = tid; i < 512; i += 128) mrow[i] = src[i * 8];
    __syncthreads();
    float acc = bro[tid];
#pragma unroll 8
    for (int k = 0; k < 512; k++)
        acc = fmaf(mrow[k], Wro[(size_t)k * 128 + tid], acc);
    out[(size_t)row * 128 + tid] = acc;
    if (row == 0 && tid == 0 && out_size > B_SZ * C_OUT) {
        out[B_SZ * C_OUT] = 1.0f - (float)g_cnt / (float)((size_t)S_LEN * B_SZ * H_SZ);
    }
}

// ---------------- launch ----------------
extern "C" void kernel_launch(void* const* d_in, const int* in_sizes, int n_in,
                              void* d_out, int out_size)
{
    const float* x    = (const float*)d_in[0];
    const float* Win  = (const float*)d_in[1];
    const float* bin  = (const float*)d_in[2];
    const float* Wtau = (const float*)d_in[3];
    const float* btl  = (const float*)d_in[4];
    const float* bt   = (const float*)d_in[5];
    const float* Wro  = (const float*)d_in[6];
    const float* bro  = (const float*)d_in[7];

    init_kernel<<<1, 1>>>();

    dim3 g1(8, 1024);   // n-tiles x m-tiles
    phase1_kernel<<<g1, 256>>>(x, Win, bin, Wtau, btl, bt);

    const int rec_smem = (512 * 64 + 512 * 8 + 8 * 512) * (int)sizeof(float) + 16; // ~164 KB
    cudaFuncSetAttribute(recurrent_kernel, cudaFuncAttributeMaxDynamicSharedMemorySize, rec_smem);
    recurrent_kernel<<<128, 256, rec_smem>>>(Wtau);

    readout_kernel<<<B_SZ, C_OUT>>>(Wro, bro, (float*)d_out, out_size);
}

// round 5
// speedup vs baseline: 1.3050x; 1.1337x over previous
#include <cuda_runtime.h>
#include <cstdint>
#include <cstdio>

#define S_LEN 1024
#define B_SZ  128
#define D_IN  256
#define H_SZ  512
#define C_OUT 128

// ---------------- device scratch ----------------
__device__ float g_T[(size_t)S_LEN * B_SZ * H_SZ];   // x@W_tau_x + b_tau_lin + b_tau
__device__ float g_G[(size_t)S_LEN * B_SZ * H_SZ];   // x@W_in + b_in
__device__ float g_buf[16 * 512 * 8];                // mem exchange: [cluster][h][b]
__device__ int   g_cnt;

__global__ void init_kernel() { g_cnt = 0; }

// ---------------- Phase 1: fused precompute GEMM (scalar fp32, R2-proven) ----------------
__global__ __launch_bounds__(256, 2) void phase1_kernel(
    const float* __restrict__ x, const float* __restrict__ Win,
    const float* __restrict__ bin, const float* __restrict__ Wtau,
    const float* __restrict__ btl, const float* __restrict__ bt)
{
    __shared__ float As[2][16][128];   // As[k][m]
    __shared__ float Bs[2][16][128];   // Bs[k][n]

    const int tid = threadIdx.x;
    const int m0 = blockIdx.y * 128;
    const int n0 = blockIdx.x * 128;
    const bool isG = (n0 < 512);
    const float* __restrict__ Bp = isG ? (Win + n0) : (Wtau + (n0 - 512));

    const int q0 = tid, q1 = tid + 256;
    const int ar0 = q0 >> 2, ak0 = (q0 & 3) * 4;
    const int ar1 = q1 >> 2, ak1 = (q1 & 3) * 4;
    const int m_0 = m0 + ar0, m_1 = m0 + ar1;
    const float* ap0 = x + ((size_t)(m_0 & 127) * 1024 + (m_0 >> 7)) * 256 + ak0;
    const float* ap1 = x + ((size_t)(m_1 & 127) * 1024 + (m_1 >> 7)) * 256 + ak1;
    const int bk0 = q0 >> 5, bn0 = (q0 & 31) * 4;
    const int bk1 = q1 >> 5, bn1 = (q1 & 31) * 4;

    const int tx = tid & 15, ty = tid >> 4;
    const int c0 = tx * 4, c1 = tx * 4 + 64;
    const int r0 = ty * 4, r1 = ty * 4 + 64;

    float acc[8][8];
#pragma unroll
    for (int i = 0; i < 8; i++)
#pragma unroll
        for (int j = 0; j < 8; j++) acc[i][j] = 0.f;

    float4 pa0 = *(const float4*)(ap0);
    float4 pa1 = *(const float4*)(ap1);
    float4 pb0 = *(const float4*)(Bp + (size_t)bk0 * 512 + bn0);
    float4 pb1 = *(const float4*)(Bp + (size_t)bk1 * 512 + bn1);

    As[0][ak0 + 0][ar0] = pa0.x; As[0][ak0 + 1][ar0] = pa0.y;
    As[0][ak0 + 2][ar0] = pa0.z; As[0][ak0 + 3][ar0] = pa0.w;
    As[0][ak1 + 0][ar1] = pa1.x; As[0][ak1 + 1][ar1] = pa1.y;
    As[0][ak1 + 2][ar1] = pa1.z; As[0][ak1 + 3][ar1] = pa1.w;
    *(float4*)&Bs[0][bk0][bn0] = pb0;
    *(float4*)&Bs[0][bk1][bn1] = pb1;
    __syncthreads();

    int p = 0;
    for (int kt = 0; kt < 16; kt++) {
        if (kt < 15) {
            const int kc = (kt + 1) * 16;
            pa0 = *(const float4*)(ap0 + kc);
            pa1 = *(const float4*)(ap1 + kc);
            pb0 = *(const float4*)(Bp + (size_t)(kc + bk0) * 512 + bn0);
            pb1 = *(const float4*)(Bp + (size_t)(kc + bk1) * 512 + bn1);
        }
#pragma unroll
        for (int k = 0; k < 16; k++) {
            float4 a0 = *(const float4*)&As[p][k][r0];
            float4 a1 = *(const float4*)&As[p][k][r1];
            float4 b0 = *(const float4*)&Bs[p][k][c0];
            float4 b1 = *(const float4*)&Bs[p][k][c1];
            float av[8] = {a0.x, a0.y, a0.z, a0.w, a1.x, a1.y, a1.z, a1.w};
            float bv[8] = {b0.x, b0.y, b0.z, b0.w, b1.x, b1.y, b1.z, b1.w};
#pragma unroll
            for (int i = 0; i < 8; i++)
#pragma unroll
                for (int j = 0; j < 8; j++)
                    acc[i][j] = fmaf(av[i], bv[j], acc[i][j]);
        }
        if (kt < 15) {
            const int np = p ^ 1;
            As[np][ak0 + 0][ar0] = pa0.x; As[np][ak0 + 1][ar0] = pa0.y;
            As[np][ak0 + 2][ar0] = pa0.z; As[np][ak0 + 3][ar0] = pa0.w;
            As[np][ak1 + 0][ar1] = pa1.x; As[np][ak1 + 1][ar1] = pa1.y;
            As[np][ak1 + 2][ar1] = pa1.z; As[np][ak1 + 3][ar1] = pa1.w;
            *(float4*)&Bs[np][bk0][bn0] = pb0;
            *(float4*)&Bs[np][bk1][bn1] = pb1;
        }
        __syncthreads();
        p ^= 1;
    }

    float* dst = isG ? g_G : g_T;
    const int coloff = isG ? n0 : (n0 - 512);
    float bias[8];
#pragma unroll
    for (int j = 0; j < 8; j++) {
        const int ncol = (j < 4) ? (c0 + j) : (c1 + j - 4);
        const int gb = coloff + ncol;
        bias[j] = isG ? bin[gb] : (btl[gb] + bt[gb]);
    }
#pragma unroll
    for (int i = 0; i < 8; i++) {
        const int mrow = m0 + ((i < 4) ? (r0 + i) : (r1 + i - 4));
        float4 o0 = make_float4(acc[i][0] + bias[0], acc[i][1] + bias[1],
                                acc[i][2] + bias[2], acc[i][3] + bias[3]);
        float4 o1 = make_float4(acc[i][4] + bias[4], acc[i][5] + bias[5],
                                acc[i][6] + bias[6], acc[i][7] + bias[7]);
        *(float4*)(dst + (size_t)mrow * 512 + coloff + c0) = o0;
        *(float4*)(dst + (size_t)mrow * 512 + coloff + c1) = o1;
    }
}

// ---------------- Phase 2: persistent recurrent kernel ----------------
__device__ __forceinline__ unsigned smem_u32_addr(const void* p) {
    unsigned a;
    asm("{ .reg .u64 t; cvta.to.shared.u64 t, %1; cvt.u32.u64 %0, t; }"
        : "=r"(a) : "l"(p));
    return a;
}

#define CLUSTER_BARRIER() \
    asm volatile("barrier.cluster.arrive.aligned;\n\tbarrier.cluster.wait.aligned;" ::: "memory")

__global__ void __cluster_dims__(8, 1, 1) __launch_bounds__(256, 1)
recurrent_kernel(const float* __restrict__ Wtau)
{
    extern __shared__ float sm[];
    float* Wm   = sm;                     // [512][64]   128 KB
    float* memT = sm + 512 * 64;          // [512][8]     16 KB  (h-major, batch contiguous)
    float* part = memT + 512 * 8;         // [8][8][64]   16 KB  (warp, batch, col)
    unsigned long long* mbar = (unsigned long long*)(part + 8 * 512);

    const int tid  = threadIdx.x;
    const int lane = tid & 31;
    const int w    = tid >> 5;
    const int r    = blockIdx.x & 7;          // rank -> column slice
    const int cl   = blockIdx.x >> 3;         // cluster index -> 8 batch rows
    const int b0   = cl * 8;

    float* gslice = g_buf + (size_t)cl * 4096 + r * 512;   // my 2KB slice in gmem

    // Load W_tau_m slice: rows 256..767, cols r*64..r*64+63
    for (int idx = tid; idx < 512 * 64; idx += 256) {
        const int k = idx >> 6, c = idx & 63;
        Wm[idx] = Wtau[(size_t)(256 + k) * 512 + r * 64 + c];
    }
    // Zero mem buffer (t=0 input)
    for (int idx = tid; idx < 512 * 8; idx += 256) memT[idx] = 0.f;

    const unsigned mbar_addr = smem_u32_addr(mbar);
    const unsigned memT_addr = smem_u32_addr(memT);
    if (tid == 0) {
        asm volatile("mbarrier.init.shared.b64 [%0], %1;"
                     :: "r"(mbar_addr), "r"(1) : "memory");
    }
    CLUSTER_BARRIER();   // mbar init + memT zero visible cluster-wide

    // elementwise role: cells (bl, ce) and (bl+1, ce)
    const int ce = tid & 63;
    const int bl = (tid >> 6) * 2;
    const int gh = r * 64 + ce;                 // global hidden col of my cells
    const int k0 = w * 64;                      // warp K-split

    float cnt = 0.f;

    for (int t = 0; t < S_LEN; t++) {
        // prefetch T/G (consumed after GEMM; hidden behind ~4k cycles)
        const size_t row0 = ((size_t)t * B_SZ + b0 + bl) * H_SZ + gh;
        const size_t row1 = ((size_t)t * B_SZ + b0 + bl + 1) * H_SZ + gh;
        const float Tv0 = g_T[row0], Gv0 = g_G[row0];
        const float Tv1 = g_T[row1], Gv1 = g_G[row1];

        // ---- GEMM: out[b][c] = sum_k memT[k][b] * Wm[k][c] (warp K-split) ----
        float acc_a[8], acc_b[8];
#pragma unroll
        for (int b = 0; b < 8; b++) { acc_a[b] = 0.f; acc_b[b] = 0.f; }

        const float* mp = memT + k0 * 8;
        const float* wp = Wm + k0 * 64;
#pragma unroll 4
        for (int kk = 0; kk < 64; kk += 4) {
            float rm[4][8];
#pragma unroll
            for (int j = 0; j < 4; j++) {
                float4 v0 = *(const float4*)(mp + (kk + j) * 8);
                float4 v1 = *(const float4*)(mp + (kk + j) * 8 + 4);
                rm[j][0] = v0.x; rm[j][1] = v0.y; rm[j][2] = v0.z; rm[j][3] = v0.w;
                rm[j][4] = v1.x; rm[j][5] = v1.y; rm[j][6] = v1.z; rm[j][7] = v1.w;
            }
#pragma unroll
            for (int j = 0; j < 4; j++) {
                const float2 wv = *(const float2*)(wp + (kk + j) * 64 + 2 * lane);
#pragma unroll
                for (int b = 0; b < 8; b++) {
                    acc_a[b] = fmaf(rm[j][b], wv.x, acc_a[b]);
                    acc_b[b] = fmaf(rm[j][b], wv.y, acc_b[b]);
                }
            }
        }
        // write warp partials: part[w][b][2*lane .. 2*lane+1] (STS.64)
#pragma unroll
        for (int b = 0; b < 8; b++) {
            *(float2*)&part[w * 512 + b * 64 + 2 * lane] = make_float2(acc_a[b], acc_b[b]);
        }
        __syncthreads();

        // ---- reduce 8 warp partials + elementwise update ----
        float s0 = 0.f, s1 = 0.f;
#pragma unroll
        for (int ww = 0; ww < 8; ww++) {
            s0 += part[ww * 512 + bl * 64 + ce];
            s1 += part[ww * 512 + (bl + 1) * 64 + ce];
        }
        const float l0 = Tv0 + s0, l1 = Tv1 + s1;
        float beta0 = 1.f / (1.f + expf(-l0));
        float beta1 = 1.f / (1.f + expf(-l1));
        beta0 = fminf(fmaxf(beta0, 0.01f), 0.99f);
        beta1 = fminf(fmaxf(beta1, 0.01f), 0.99f);
        const float mo0 = memT[gh * 8 + bl];
        const float mo1 = memT[gh * 8 + bl + 1];
        float mn0 = fmaf(beta0, mo0, Gv0);
        float mn1 = fmaf(beta1, mo1, Gv1);
        const float sp0 = ((mn0 - 1.0f) > 0.0f) ? 1.f : 0.f;
        const float sp1 = ((mn1 - 1.0f) > 0.0f) ? 1.f : 0.f;
        mn0 -= sp0; mn1 -= sp1;
        cnt += sp0 + sp1;

        // ---- publish my 2 values to the gmem slice (also the final output) ----
        asm volatile("st.global.cg.v2.f32 [%0], {%1, %2};"
                     :: "l"(gslice + ce * 8 + bl), "f"(mn0), "f"(mn1) : "memory");

        if (t < S_LEN - 1) {
            // order my STG before the async-proxy TMA reads, cluster-wide
            asm volatile("fence.proxy.async;" ::: "memory");
            if (tid == 0) {
                asm volatile("mbarrier.arrive.expect_tx.shared.b64 _, [%0], %1;"
                             :: "r"(mbar_addr), "r"(16384) : "memory");
            }
            CLUSTER_BARRIER();   // all slices in L2, all mbars armed, all memT reads done
            if (tid == 0) {
                // multicast my slice into memT[r*64*8 ..] of ALL 8 CTAs (2KB)
                asm volatile(
                    "cp.async.bulk.shared::cluster.global.mbarrier::complete_tx::bytes.multicast::cluster"
                    " [%0], [%1], %2, [%3], %4;"
                    :: "r"(memT_addr + (unsigned)(r * 512 * 4)), "l"(gslice),
                       "r"(2048), "r"(mbar_addr), "h"((unsigned short)0xFF)
                    : "memory");
            }
            // wait for all 8 slices (16KB) to land in my memT
            {
                const unsigned ph = (unsigned)(t & 1);
                asm volatile(
                    "{\n\t"
                    ".reg .pred P;\n\t"
                    "W_%=:\n\t"
                    "mbarrier.try_wait.parity.acquire.cta.shared::cta.b64 P, [%0], %1, 0x989680;\n\t"
                    "@P bra D_%=;\n\t"
                    "bra W_%=;\n\t"
                    "D_%=:\n\t"
                    "}"
                    :: "r"(mbar_addr), "r"(ph) : "memory");
            }
        }
    }

    // spike-count reduction
    __syncthreads();
    part[tid] = cnt;
    __syncthreads();
    if (tid < 128) part[tid] += part[tid + 128];
    __syncthreads();
    if (tid < 64) part[tid] += part[tid + 64];
    __syncthreads();
    if (tid < 32) {
        float v = part[tid] + part[tid + 32];
#pragma unroll
        for (int o = 16; o > 0; o >>= 1) v += __shfl_down_sync(0xffffffffu, v, o);
        if (tid == 0) atomicAdd(&g_cnt, (int)(v + 0.5f));
    }
    CLUSTER_BARRIER();   // clean cluster exit
}

// ---------------- Phase 3: readout GEMM + sparsity ----------------
// final mem: mem[b][h] = g_buf[(b>>3)*4096 + h*8 + (b&7)]
__global__ void readout_kernel(const float* __restrict__ Wro, const float* __restrict__ bro,
                               float* __restrict__ out, int out_size)
{
    __shared__ float mrow[512];
    const int row = blockIdx.x;
    const int tid = threadIdx.x;   // 128
    const float* src = g_buf + (size_t)(row >> 3) * 4096 + (row & 7);
    for (int i = tid; i < 512; i += 128) mrow[i] = src[i * 8];
    __syncthreads();
    float acc = bro[tid];
#pragma unroll 8
    for (int k = 0; k < 512; k++)
        acc = fmaf(mrow[k], Wro[(size_t)k * 128 + tid], acc);
    out[(size_t)row * 128 + tid] = acc;
    if (row == 0 && tid == 0 && out_size > B_SZ * C_OUT) {
        out[B_SZ * C_OUT] = 1.0f - (float)g_cnt / (float)((size_t)S_LEN * B_SZ * H_SZ);
    }
}

// ---------------- launch ----------------
extern "C" void kernel_launch(void* const* d_in, const int* in_sizes, int n_in,
                              void* d_out, int out_size)
{
    const float* x    = (const float*)d_in[0];
    const float* Win  = (const float*)d_in[1];
    const float* bin  = (const float*)d_in[2];
    const float* Wtau = (const float*)d_in[3];
    const float* btl  = (const float*)d_in[4];
    const float* bt   = (const float*)d_in[5];
    const float* Wro  = (const float*)d_in[6];
    const float* bro  = (const float*)d_in[7];

    init_kernel<<<1, 1>>>();

    dim3 g1(8, 1024);   // n-tiles x m-tiles
    phase1_kernel<<<g1, 256>>>(x, Win, bin, Wtau, btl, bt);

    const int rec_smem = (512 * 64 + 512 * 8 + 8 * 512) * (int)sizeof(float) + 32; // ~160 KB
    cudaFuncSetAttribute(recurrent_kernel, cudaFuncAttributeMaxDynamicSharedMemorySize, rec_smem);
    recurrent_kernel<<<128, 256, rec_smem>>>(Wtau);

    readout_kernel<<<B_SZ, C_OUT>>>(Wro, bro, (float*)d_out, out_size);
}